// round 9
// baseline (speedup 1.0000x reference)
#include <cuda_runtime.h>
#include <math.h>

#define H 1024
#define W 1024
#define HW (H*W)
#define NSX 19          // ceil(1024/56)
#define NSY 16          // 1024/64
#define SPP (NSX*NSY)   // strips per image-pair = 304
#define NT 256
#define WPB (NT/32)

typedef unsigned long long u64;

__device__ int g_count = 0;
__device__ int g_ticket = 0;

__device__ __forceinline__ u64 pk(float lo, float hi) {
    u64 r; asm("mov.b64 %0,{%1,%2};" : "=l"(r) : "f"(lo), "f"(hi)); return r;
}
__device__ __forceinline__ void upk(u64 v, float& lo, float& hi) {
    asm("mov.b64 {%0,%1},%2;" : "=f"(lo), "=f"(hi) : "l"(v));
}
__device__ __forceinline__ u64 fadd2(u64 a, u64 b) {
    u64 r; asm("add.rn.f32x2 %0,%1,%2;" : "=l"(r) : "l"(a), "l"(b)); return r;
}
__device__ __forceinline__ u64 fmul2(u64 a, u64 b) {
    u64 r; asm("mul.rn.f32x2 %0,%1,%2;" : "=l"(r) : "l"(a), "l"(b)); return r;
}
__device__ __forceinline__ u64 ffma2(u64 a, u64 b, u64 c) {
    u64 r; asm("fma.rn.f32x2 %0,%1,%2,%3;" : "=l"(r) : "l"(a), "l"(b), "l"(c)); return r;
}
__device__ __forceinline__ u64 fneg2(u64 a) { return a ^ 0x8000000080000000ULL; }
__device__ __forceinline__ u64 fsub2(u64 a, u64 b) { return fadd2(a, fneg2(b)); }

__device__ __forceinline__ int reflecti(int c, int n) {
    if (c < 0) c = -c;
    if (c >= n) c = 2*n - 2 - c;
    return c;
}

#define GW0 0.05448868454964294f
#define GW1 0.24420134723186663f
#define GW2 0.4026199364369709f
#define T_LO 0.41421356237309503f
#define T_HI 2.414213562373095f
#define TH2  0.009999f

__device__ __forceinline__ int ax_code(float gx, float gy) {
    float axv = fabsf(gx), ayv = fabsf(gy);
    if (ayv <= T_LO * axv) return 0;                                   // H axis
    if (ayv >= T_HI * axv) return 1;                                   // V axis
    return ((__float_as_int(gx) ^ __float_as_int(gy)) >= 0) ? 2 : 3;   // diagonals
}

__device__ __forceinline__ u64 tap5(u64 t0, u64 t1, u64 t2, u64 t3, u64 t4,
                                    u64 K0, u64 K1, u64 K2) {
    u64 acc = fmul2(fadd2(t0, t4), K0);
    acc = ffma2(fadd2(t1, t3), K1, acc);
    return ffma2(t2, K2, acc);
}

// NMS for one image-lane: neighbors selected by 2-bit axis code
__device__ __forceinline__ bool nms1(float c, float L, float R, float U, float D,
                                     float UL, float UR, float DL, float DR, int code) {
    float n1 = (code == 0) ? L : (code == 1) ? U : (code == 2) ? UR : UL;
    float n2 = (code == 0) ? R : (code == 1) ? D : (code == 2) ? DL : DR;
    return (c > n1) & (c > n2) & (c > TH2);
}

__global__ __launch_bounds__(NT)
void edge_loss_kernel(const float* __restrict__ op, const float* __restrict__ gt,
                      float* __restrict__ out, float inv_n, int total_warps)
{
    const int lane = threadIdx.x & 31;
    const int w = blockIdx.x * WPB + (threadIdx.x >> 5);
    if (w >= total_warps) return;

    const int n  = w / SPP;
    const int s  = w - n * SPP;
    const int sy = s / NSX;
    const int sx = s - sy * NSX;
    const int xb = sx * 56 - 4;
    const int ys = sy * 64;

    const float* __restrict__ po = op + (size_t)n * 3 * HW;
    const float* __restrict__ pg = gt + (size_t)n * 3 * HW;

    const bool xedge = (sx == 0) || (sx == NSX - 1);
    const int  c0  = xb + 2 * lane;
    const int  rc0 = reflecti(c0, W), rc1 = reflecti(c0 + 1, W);
    const bool vlane = (lane >= 2) && (lane <= 29);
    const bool v0 = vlane && ((unsigned)c0 < W);
    const bool v1 = vlane && ((unsigned)(c0 + 1) < W);
    const bool lok = (c0 - 1 >= 0);       // sobel x-clamp left  (col0's left nbr)
    const bool rok = (c0 + 2 <= W - 1);   // sobel x-clamp right (col1's right nbr)
    const bool x0ok = ((unsigned)c0 < W);
    const bool x1ok = ((unsigned)(c0 + 1) < W);

    const u64 K0c = pk(GW0, GW0);
    const u64 K1c = pk(GW1, GW1);
    const u64 K2c = pk(GW2, GW2);

    // --- rolling windows ---
    u64 h0[2], h1[2], h2[2], h3[2], h4[2];   // hblur rows cy-2..cy+2
    u64 va[2], vb_[2], vc[2];                // blurred rows kv-2, kv-1, kv
    u64 m0[2], m1[2], m2[2];                 // msq rows r-1, r, r+1
    unsigned codes1 = 0, codes2 = 0;
    m0[0]=m0[1]=m1[0]=m1[1]=m2[0]=m2[1]=0ULL;

    u64 g[2];
    #define LOADGRAY(gr, gdst) do {                                               \
        int yy_ = reflecti((gr), H);                                              \
        const float* ro_ = po + yy_ * W;                                          \
        const float* rg_ = pg + yy_ * W;                                          \
        float ao0_, ao1_, ag0_, ag1_;                                             \
        if (!xedge) {                                                             \
            float2 r_o = *(const float2*)(ro_ + c0);                              \
            float2 g_o = *(const float2*)(ro_ + HW + c0);                         \
            float2 b_o = *(const float2*)(ro_ + 2*HW + c0);                       \
            float2 r_g = *(const float2*)(rg_ + c0);                              \
            float2 g_g = *(const float2*)(rg_ + HW + c0);                         \
            float2 b_g = *(const float2*)(rg_ + 2*HW + c0);                       \
            ao0_ = fmaf(0.299f, r_o.x, fmaf(0.587f, g_o.x, 0.114f*b_o.x));        \
            ao1_ = fmaf(0.299f, r_o.y, fmaf(0.587f, g_o.y, 0.114f*b_o.y));        \
            ag0_ = fmaf(0.299f, r_g.x, fmaf(0.587f, g_g.x, 0.114f*b_g.x));        \
            ag1_ = fmaf(0.299f, r_g.y, fmaf(0.587f, g_g.y, 0.114f*b_g.y));        \
        } else {                                                                  \
            ao0_ = fmaf(0.299f, ro_[rc0], fmaf(0.587f, ro_[HW+rc0], 0.114f*ro_[2*HW+rc0])); \
            ao1_ = fmaf(0.299f, ro_[rc1], fmaf(0.587f, ro_[HW+rc1], 0.114f*ro_[2*HW+rc1])); \
            ag0_ = fmaf(0.299f, rg_[rc0], fmaf(0.587f, rg_[HW+rc0], 0.114f*rg_[2*HW+rc0])); \
            ag1_ = fmaf(0.299f, rg_[rc1], fmaf(0.587f, rg_[HW+rc1], 0.114f*rg_[2*HW+rc1])); \
        }                                                                         \
        (gdst)[0] = pk(ao0_, ag0_);                                               \
        (gdst)[1] = pk(ao1_, ag1_);                                               \
    } while (0)

    #define HBLUR(gsrc, hdst) do {                                                \
        u64 gm0_ = __shfl_up_sync(0xffffffffu, (gsrc)[0], 1);                     \
        u64 gm1_ = __shfl_up_sync(0xffffffffu, (gsrc)[1], 1);                     \
        u64 gp0_ = __shfl_down_sync(0xffffffffu, (gsrc)[0], 1);                   \
        u64 gp1_ = __shfl_down_sync(0xffffffffu, (gsrc)[1], 1);                   \
        (hdst)[0] = tap5(gm0_, gm1_, (gsrc)[0], (gsrc)[1], gp0_, K0c, K1c, K2c);  \
        (hdst)[1] = tap5(gm1_, (gsrc)[0], (gsrc)[1], gp0_, gp1_, K0c, K1c, K2c);  \
    } while (0)

    #define HSHIFT_LOAD(row) do {                                                \
        h0[0]=h1[0]; h0[1]=h1[1]; h1[0]=h2[0]; h1[1]=h2[1];                       \
        h2[0]=h3[0]; h2[1]=h3[1]; h3[0]=h4[0]; h3[1]=h4[1];                       \
        LOADGRAY((row), g); HBLUR(g, h4);                                         \
    } while (0)

    #define VTAP(vdst) do {                                                      \
        (vdst)[0] = tap5(h0[0], h1[0], h2[0], h3[0], h4[0], K0c, K1c, K2c);       \
        (vdst)[1] = tap5(h0[1], h1[1], h2[1], h3[1], h4[1], K0c, K1c, K2c);       \
    } while (0)

    // --- prologue: hblur window for first blurred row SV(ys-2) ---
    int cy = ys - 2; if (cy < 0) cy = 0;
    LOADGRAY(cy - 2, g); HBLUR(g, h0);
    LOADGRAY(cy - 1, g); HBLUR(g, h1);
    LOADGRAY(cy + 0, g); HBLUR(g, h2);
    LOADGRAY(cy + 1, g); HBLUR(g, h3);
    LOADGRAY(cy + 2, g); HBLUR(g, h4);
    u64 vbv[2];
    VTAP(vbv);
    va[0] = vbv[0]; va[1] = vbv[1];         // SV(ys-2)
    {   // SV(ys-1)
        int cyn = min(ys - 1, H - 1);
        if (cyn > cy) { HSHIFT_LOAD(cyn + 2); cy = cyn; VTAP(vbv); }
        vb_[0] = vbv[0]; vb_[1] = vbv[1];
    }

    const u64 TWO = pk(2.0f, 2.0f);
    int cnt = 0;

    // --- main loop: kv = ys .. ys+65 ---
    for (int kv = ys; kv <= ys + 65; kv++) {
        int cyn = min(kv, H - 1);
        if (cyn > cy) { HSHIFT_LOAD(cyn + 2); cy = cyn; VTAP(vbv); }
        vc[0] = vbv[0]; vc[1] = vbv[1];     // SV(kv)

        // shift msq window; codes of row kv-2 become the NMS-center codes
        m0[0]=m1[0]; m0[1]=m1[1]; m1[0]=m2[0]; m1[1]=m2[1];
        codes1 = codes2;

        // msq + axis codes for row m = kv-1
        int m = kv - 1;
        if ((unsigned)m < H) {
            u64 aL = __shfl_up_sync(0xffffffffu, va[1], 1);
            u64 aR = __shfl_down_sync(0xffffffffu, va[0], 1);
            u64 bL = __shfl_up_sync(0xffffffffu, vb_[1], 1);
            u64 bR = __shfl_down_sync(0xffffffffu, vb_[0], 1);
            u64 cL = __shfl_up_sync(0xffffffffu, vc[1], 1);
            u64 cR = __shfl_down_sync(0xffffffffu, vc[0], 1);
            if (!lok) { aL = va[0]; bL = vb_[0]; cL = vc[0]; }   // edge-clamp x
            if (!rok) { aR = va[1]; bR = vb_[1]; cR = vc[1]; }

            u64 gx0 = ffma2(fsub2(vb_[1], bL), TWO, fadd2(fsub2(va[1], aL), fsub2(vc[1], cL)));
            u64 gy0 = ffma2(fsub2(vc[0], va[0]), TWO, fadd2(fsub2(cL, aL), fsub2(vc[1], va[1])));
            u64 gx1 = ffma2(fsub2(bR, vb_[0]), TWO, fadd2(fsub2(aR, va[0]), fsub2(cR, vc[0])));
            u64 gy1 = ffma2(fsub2(vc[1], va[1]), TWO, fadd2(fsub2(vc[0], va[0]), fsub2(cR, aR)));

            u64 q0 = ffma2(gx0, gx0, fmul2(gy0, gy0));
            u64 q1 = ffma2(gx1, gx1, fmul2(gy1, gy1));
            m2[0] = x0ok ? q0 : 0ULL;
            m2[1] = x1ok ? q1 : 0ULL;

            float a, b, c, d;
            upk(gx0, a, b); upk(gy0, c, d);
            unsigned cc = (unsigned)ax_code(a, c) | ((unsigned)ax_code(b, d) << 2);
            upk(gx1, a, b); upk(gy1, c, d);
            cc |= ((unsigned)ax_code(a, c) << 4) | ((unsigned)ax_code(b, d) << 6);
            codes2 = cc;
        } else {
            m2[0] = 0ULL; m2[1] = 0ULL; codes2 = 0;
        }

        // NMS for row r = kv-2
        if (kv >= ys + 2) {
            u64 L0 = __shfl_up_sync(0xffffffffu, m0[1], 1);
            u64 R0 = __shfl_down_sync(0xffffffffu, m0[0], 1);
            u64 L1 = __shfl_up_sync(0xffffffffu, m1[1], 1);
            u64 R1 = __shfl_down_sync(0xffffffffu, m1[0], 1);
            u64 L2 = __shfl_up_sync(0xffffffffu, m2[1], 1);
            u64 R2 = __shfl_down_sync(0xffffffffu, m2[0], 1);

            float cl, ch, Ll, Lh, Rl, Rh, Ul, Uh, Dl, Dh;
            float ULl, ULh, URl, URh, DLl, DLh, DRl, DRh;

            // col0: L=L1, R=m1[1], U=m0[0], D=m2[0], UL=L0, UR=m0[1], DL=L2, DR=m2[1]
            upk(m1[0], cl, ch); upk(L1, Ll, Lh); upk(m1[1], Rl, Rh);
            upk(m0[0], Ul, Uh); upk(m2[0], Dl, Dh);
            upk(L0, ULl, ULh);  upk(m0[1], URl, URh);
            upk(L2, DLl, DLh);  upk(m2[1], DRl, DRh);
            {
                bool eo = nms1(cl, Ll, Rl, Ul, Dl, ULl, URl, DLl, DRl, (int)(codes1 & 3u));
                bool eg = nms1(ch, Lh, Rh, Uh, Dh, ULh, URh, DLh, DRh, (int)((codes1 >> 2) & 3u));
                cnt += (int)((eo != eg) & v0);
            }
            // col1: L=m1[0], R=R1, U=m0[1], D=m2[1], UL=m0[0], UR=R0, DL=m2[0], DR=R2
            upk(m1[1], cl, ch); upk(m1[0], Ll, Lh); upk(R1, Rl, Rh);
            upk(m0[1], Ul, Uh); upk(m2[1], Dl, Dh);
            upk(m0[0], ULl, ULh); upk(R0, URl, URh);
            upk(m2[0], DLl, DLh); upk(R2, DRl, DRh);
            {
                bool eo = nms1(cl, Ll, Rl, Ul, Dl, ULl, URl, DLl, DRl, (int)((codes1 >> 4) & 3u));
                bool eg = nms1(ch, Lh, Rh, Uh, Dh, ULh, URh, DLh, DRh, (int)((codes1 >> 6) & 3u));
                cnt += (int)((eo != eg) & v1);
            }
        }

        // shift blurred window
        va[0] = vb_[0]; va[1] = vb_[1];
        vb_[0] = vc[0]; vb_[1] = vc[1];
    }

    // --- warp reduce + fused finalize ---
    #pragma unroll
    for (int o = 16; o > 0; o >>= 1)
        cnt += __shfl_down_sync(0xffffffffu, cnt, o);
    if (lane == 0) {
        atomicAdd(&g_count, cnt);
        __threadfence();
        int t = atomicAdd(&g_ticket, 1);
        if (t == total_warps - 1) {
            out[0] = (float)atomicAdd(&g_count, 0) * inv_n;
            g_count = 0;
            g_ticket = 0;
        }
    }
}

extern "C" void kernel_launch(void* const* d_in, const int* in_sizes, int n_in,
                              void* d_out, int out_size)
{
    const float* op = (const float*)d_in[0];
    const float* gt = (const float*)d_in[1];
    float* out = (float*)d_out;

    int batch = in_sizes[0] / (3 * HW);
    int total_warps = batch * SPP;
    int blocks = (total_warps + WPB - 1) / WPB;
    float inv_n = 1.0f / ((float)batch * HW);

    edge_loss_kernel<<<blocks, NT>>>(op, gt, out, inv_n, total_warps);
}